// round 3
// baseline (speedup 1.0000x reference)
#include <cuda_runtime.h>

// SNN XOR net — alu-pipe reduction round.
// sneg in {-1,0} from ONE compare+select per neuron serves both:
//   reset:  m = fma(beta,m,cur) + sneg_prev        (FADD, fma pipe; exact)
//   output: acc = fmaf(sneg, -w2, acc)             (== acc + w2 bit-exactly)
// Output value o = 0 - sneg2 (FADD, fma pipe) instead of a second select.
// No f32x2 packing (R2 showed the pack/unpack movs land on the alu pipe).

#define T_STEPS 20
#define BETA 0.9f
#define THR 1.0f

__global__ void __launch_bounds__(256) snn_xornet_kernel(
    const float* __restrict__ x,    // [B,2]
    const float* __restrict__ w1,   // [4,2]
    const float* __restrict__ w2,   // [1,4]
    float* __restrict__ out,        // [T,B]
    int B)
{
    const int i = blockIdx.x * blockDim.x + threadIdx.x;  // group of 4 elems
    if (i * 4 >= B) return;

    float w1r[4][2];
#pragma unroll
    for (int h = 0; h < 4; h++) {
        w1r[h][0] = __ldg(&w1[2 * h + 0]);
        w1r[h][1] = __ldg(&w1[2 * h + 1]);
    }
    float w2n[4];
#pragma unroll
    for (int h = 0; h < 4; h++) w2n[h] = -__ldg(&w2[h]);  // negated for sneg*(-w2)

    const float4 xa = reinterpret_cast<const float4*>(x)[2 * i + 0];
    const float4 xb = reinterpret_cast<const float4*>(x)[2 * i + 1];
    const float xs[4][2] = {{xa.x, xa.y}, {xa.z, xa.w}, {xb.x, xb.y}, {xb.z, xb.w}};

    // cur = x @ w1^T (identical rounding to R1)
    float cur[4][4];
#pragma unroll
    for (int j = 0; j < 4; j++)
#pragma unroll
        for (int h = 0; h < 4; h++)
            cur[j][h] = fmaf(xs[j][0], w1r[h][0], xs[j][1] * w1r[h][1]);

    // State: membranes + sneg (-1 if spiked last step, else 0)
    float m1[4][4], s1[4][4];
    float m2[4], s2[4];
#pragma unroll
    for (int j = 0; j < 4; j++) {
        m2[j] = 0.0f; s2[j] = 0.0f;
#pragma unroll
        for (int h = 0; h < 4; h++) { m1[j][h] = 0.0f; s1[j][h] = 0.0f; }
    }

    float4* out4 = reinterpret_cast<float4*>(out);
    const int Bq = B >> 2;

#pragma unroll
    for (int t = 0; t < T_STEPS; t++) {
        float o[4];
#pragma unroll
        for (int j = 0; j < 4; j++) {
            float acc = 0.0f;
#pragma unroll
            for (int h = 0; h < 4; h++) {
                // membrane: fma then add of {-1,0} reset — bit-identical to
                // fma(beta,m,cur) - reset*THR with THR=1
                const float m = fmaf(BETA, m1[j][h], cur[j][h]) + s1[j][h];
                m1[j][h] = m;
                const float s = (m > THR) ? -1.0f : 0.0f;   // FSETP + FSEL
                s1[j][h] = s;
                // acc + w2[h] exactly when spiked ((-1)*(-w2) rounds once)
                acc = fmaf(s, w2n[h], acc);
            }
            const float mo = fmaf(BETA, m2[j], acc) + s2[j];
            m2[j] = mo;
            const float so = (mo > THR) ? -1.0f : 0.0f;
            s2[j] = so;
            o[j] = 0.0f - so;                                // FADD, fma pipe
        }
        float4 v;
        v.x = o[0]; v.y = o[1]; v.z = o[2]; v.w = o[3];
        out4[(size_t)t * Bq + i] = v;
    }
}

extern "C" void kernel_launch(void* const* d_in, const int* in_sizes, int n_in,
                              void* d_out, int out_size) {
    const float* x  = (const float*)d_in[0];   // [B,2]
    const float* w1 = (const float*)d_in[1];   // [4,2]
    const float* w2 = (const float*)d_in[2];   // [1,4]
    float* out = (float*)d_out;                // [T,B,1]

    const int B = in_sizes[0] / 2;
    const int groups = B / 4;
    const int threads = 256;
    const int blocks = (groups + threads - 1) / threads;
    snn_xornet_kernel<<<blocks, threads>>>(x, w1, w2, out, B);
}

// round 4
// speedup vs baseline: 1.3471x; 1.3471x over previous
#include <cuda_runtime.h>

// SNN XOR net — FSET round.
// set.gt.f32.f32 (SASS FSET) gives spike as 1.0f/0.0f in ONE alu op, feeding:
//   reset:  m = m - spos            (FADD, fma pipe; exact, == m + (-1)*spike)
//   layer2: acc = fma(spos, w2, acc) (exact: 1*w2 or 0)
//   output: o = spos                 (stored directly, no extra op)
// 2 elements/thread -> ~40 regs -> high occupancy; arithmetic rounding is
// bit-identical to the best passing kernel (expect rel_err 0.0008596012).

#define T_STEPS 20
#define BETA 0.9f
#define THR 1.0f

__device__ __forceinline__ float fset_gt(float a, float b) {
    float d;
    asm("set.gt.f32.f32 %0, %1, %2;" : "=f"(d) : "f"(a), "f"(b));
    return d;  // 1.0f if a > b else 0.0f
}

__global__ void __launch_bounds__(256) snn_xornet_kernel(
    const float* __restrict__ x,    // [B,2]
    const float* __restrict__ w1,   // [4,2]
    const float* __restrict__ w2,   // [1,4]
    float* __restrict__ out,        // [T,B]
    int B)
{
    const int i = blockIdx.x * blockDim.x + threadIdx.x;  // group of 2 elems
    if (i * 2 >= B) return;

    float w1r[4][2];
#pragma unroll
    for (int h = 0; h < 4; h++) {
        w1r[h][0] = __ldg(&w1[2 * h + 0]);
        w1r[h][1] = __ldg(&w1[2 * h + 1]);
    }
    float w2r[4];
#pragma unroll
    for (int h = 0; h < 4; h++) w2r[h] = __ldg(&w2[h]);

    // x for 2 batch elements: 4 contiguous floats
    const float4 xv = reinterpret_cast<const float4*>(x)[i];
    const float xs[2][2] = {{xv.x, xv.y}, {xv.z, xv.w}};

    // cur = x @ w1^T (identical rounding to previous passing kernels)
    float cur[2][4];
#pragma unroll
    for (int j = 0; j < 2; j++)
#pragma unroll
        for (int h = 0; h < 4; h++)
            cur[j][h] = fmaf(xs[j][0], w1r[h][0], xs[j][1] * w1r[h][1]);

    // State: membranes + spos (1.0 if spiked last step else 0.0)
    float m1[2][4], s1[2][4];
    float m2[2], s2[2];
#pragma unroll
    for (int j = 0; j < 2; j++) {
        m2[j] = 0.0f; s2[j] = 0.0f;
#pragma unroll
        for (int h = 0; h < 4; h++) { m1[j][h] = 0.0f; s1[j][h] = 0.0f; }
    }

    float2* out2 = reinterpret_cast<float2*>(out);
    const int Bh = B >> 1;

#pragma unroll
    for (int t = 0; t < T_STEPS; t++) {
        float2 v;
#pragma unroll
        for (int j = 0; j < 2; j++) {
            float acc = 0.0f;
#pragma unroll
            for (int h = 0; h < 4; h++) {
                // m = fma(beta,m,cur) - spike_prev  (bit-identical to -reset*THR)
                float m = fmaf(BETA, m1[j][h], cur[j][h]) - s1[j][h];
                m1[j][h] = m;
                const float sp = fset_gt(m, THR);        // FSET: 1.0/0.0
                s1[j][h] = sp;
                acc = fmaf(sp, w2r[h], acc);             // exact: +w2 or +0
            }
            const float mo = fmaf(BETA, m2[j], acc) - s2[j];
            m2[j] = mo;
            const float so = fset_gt(mo, THR);
            s2[j] = so;
            if (j == 0) v.x = so; else v.y = so;
        }
        out2[(size_t)t * Bh + i] = v;
    }
}

extern "C" void kernel_launch(void* const* d_in, const int* in_sizes, int n_in,
                              void* d_out, int out_size) {
    const float* x  = (const float*)d_in[0];   // [B,2]
    const float* w1 = (const float*)d_in[1];   // [4,2]
    const float* w2 = (const float*)d_in[2];   // [1,4]
    float* out = (float*)d_out;                // [T,B,1]

    const int B = in_sizes[0] / 2;
    const int groups = B / 2;
    const int threads = 256;
    const int blocks = (groups + threads - 1) / threads;
    snn_xornet_kernel<<<blocks, threads>>>(x, w1, w2, out, B);
}

// round 5
// speedup vs baseline: 1.4358x; 1.0659x over previous
#include <cuda_runtime.h>

// SNN XOR net — wave-quantization round.
// Body is bit-identical to the R4 (20.2us) kernel: FSET spike as 1.0/0.0,
// m = fma(beta,m,cur) - s_prev, acc = fma(s, w2, acc), o = s.
// Launch-shape change: block=128 + 30KB dynamic-smem ballast caps residency
// at 7 blocks/SM -> chip wave = 1036 blocks; grid=4096 -> 3.954 waves
// (98.8% average fill) instead of 1.73 waves (86.5%).

#define T_STEPS 20
#define BETA 0.9f
#define THR 1.0f

__device__ __forceinline__ float fset_gt(float a, float b) {
    float d;
    asm("set.gt.f32.f32 %0, %1, %2;" : "=f"(d) : "f"(a), "f"(b));
    return d;  // 1.0f if a > b else 0.0f
}

__global__ void __launch_bounds__(128) snn_xornet_kernel(
    const float* __restrict__ x,    // [B,2]
    const float* __restrict__ w1,   // [4,2]
    const float* __restrict__ w2,   // [1,4]
    float* __restrict__ out,        // [T,B]
    int B)
{
    extern __shared__ float smem_ballast[];   // occupancy ballast, never read
    const int i = blockIdx.x * blockDim.x + threadIdx.x;  // group of 2 elems
    if (i * 2 >= B) return;
    // Keep the ballast alive without ever executing the store (B > 0 always).
    if (B < 0) smem_ballast[threadIdx.x] = (float)i;

    float w1r[4][2];
#pragma unroll
    for (int h = 0; h < 4; h++) {
        w1r[h][0] = __ldg(&w1[2 * h + 0]);
        w1r[h][1] = __ldg(&w1[2 * h + 1]);
    }
    float w2r[4];
#pragma unroll
    for (int h = 0; h < 4; h++) w2r[h] = __ldg(&w2[h]);

    // x for 2 batch elements: 4 contiguous floats
    const float4 xv = reinterpret_cast<const float4*>(x)[i];
    const float xs[2][2] = {{xv.x, xv.y}, {xv.z, xv.w}};

    // cur = x @ w1^T (identical rounding to previous passing kernels)
    float cur[2][4];
#pragma unroll
    for (int j = 0; j < 2; j++)
#pragma unroll
        for (int h = 0; h < 4; h++)
            cur[j][h] = fmaf(xs[j][0], w1r[h][0], xs[j][1] * w1r[h][1]);

    // State: membranes + spos (1.0 if spiked last step else 0.0)
    float m1[2][4], s1[2][4];
    float m2[2], s2[2];
#pragma unroll
    for (int j = 0; j < 2; j++) {
        m2[j] = 0.0f; s2[j] = 0.0f;
#pragma unroll
        for (int h = 0; h < 4; h++) { m1[j][h] = 0.0f; s1[j][h] = 0.0f; }
    }

    float2* out2 = reinterpret_cast<float2*>(out);
    const int Bh = B >> 1;

#pragma unroll
    for (int t = 0; t < T_STEPS; t++) {
        float2 v;
#pragma unroll
        for (int j = 0; j < 2; j++) {
            float acc = 0.0f;
#pragma unroll
            for (int h = 0; h < 4; h++) {
                float m = fmaf(BETA, m1[j][h], cur[j][h]) - s1[j][h];
                m1[j][h] = m;
                const float sp = fset_gt(m, THR);        // FSET: 1.0/0.0
                s1[j][h] = sp;
                acc = fmaf(sp, w2r[h], acc);             // exact: +w2 or +0
            }
            const float mo = fmaf(BETA, m2[j], acc) - s2[j];
            m2[j] = mo;
            const float so = fset_gt(mo, THR);
            s2[j] = so;
            if (j == 0) v.x = so; else v.y = so;
        }
        out2[(size_t)t * Bh + i] = v;
    }
}

extern "C" void kernel_launch(void* const* d_in, const int* in_sizes, int n_in,
                              void* d_out, int out_size) {
    const float* x  = (const float*)d_in[0];   // [B,2]
    const float* w1 = (const float*)d_in[1];   // [4,2]
    const float* w2 = (const float*)d_in[2];   // [1,4]
    float* out = (float*)d_out;                // [T,B,1]

    const int B = in_sizes[0] / 2;
    const int groups = B / 2;
    const int threads = 128;
    const int blocks = (groups + threads - 1) / threads;
    const size_t ballast = 30 * 1024;  // caps residency at 7 blocks/SM
    snn_xornet_kernel<<<blocks, threads, ballast>>>(x, w1, w2, out, B);
}